// round 12
// baseline (speedup 1.0000x reference)
#include <cuda_runtime.h>
#include <cuda_fp16.h>
#include <cuda_bf16.h>
#include <stdint.h>
#include <math.h>

#define N_NODES 8192
#define IN_F    512
#define OUT_F   256

// support as fp16, TRANSPOSED: [OUT_F][N_NODES]
__device__ uint16_t g_supT[OUT_F * N_NODES];

__device__ __forceinline__ uint32_t smem_u32(const void* p) {
    uint32_t a;
    asm("{ .reg .u64 t; cvta.to.shared.u64 t, %1; cvt.u32.u64 %0, t; }" : "=r"(a) : "l"(p));
    return a;
}
__device__ __forceinline__ void ldsm_x4(uint32_t r[4], uint32_t addr) {
    asm volatile("ldmatrix.sync.aligned.m8n8.x4.shared.b16 {%0,%1,%2,%3}, [%4];"
                 : "=r"(r[0]), "=r"(r[1]), "=r"(r[2]), "=r"(r[3]) : "r"(addr));
}
__device__ __forceinline__ void mma16816h(float c[4],
                                          uint32_t a0, uint32_t a1, uint32_t a2, uint32_t a3,
                                          uint32_t b0, uint32_t b1) {
    asm volatile(
        "mma.sync.aligned.m16n8k16.row.col.f32.f16.f16.f32 "
        "{%0,%1,%2,%3}, {%4,%5,%6,%7}, {%8,%9}, {%0,%1,%2,%3};"
        : "+f"(c[0]), "+f"(c[1]), "+f"(c[2]), "+f"(c[3])
        : "r"(a0), "r"(a1), "r"(a2), "r"(a3), "r"(b0), "r"(b1));
}
__device__ __forceinline__ void mma16816(float c[4],
                                         uint32_t a0, uint32_t a1, uint32_t a2, uint32_t a3,
                                         uint32_t b0, uint32_t b1) {
    asm volatile(
        "mma.sync.aligned.m16n8k16.row.col.f32.bf16.bf16.f32 "
        "{%0,%1,%2,%3}, {%4,%5,%6,%7}, {%8,%9}, {%0,%1,%2,%3};"
        : "+f"(c[0]), "+f"(c[1]), "+f"(c[2]), "+f"(c[3])
        : "r"(a0), "r"(a1), "r"(a2), "r"(a3), "r"(b0), "r"(b1));
}
__device__ __forceinline__ void split2(float x, float y, uint32_t& hi, uint32_t& lo) {
    __nv_bfloat162 h = __floats2bfloat162_rn(x, y);
    float2 hf = __bfloat1622float2(h);
    __nv_bfloat162 l = __floats2bfloat162_rn(x - hf.x, y - hf.y);
    hi = *reinterpret_cast<uint32_t*>(&h);
    lo = *reinterpret_cast<uint32_t*>(&l);
}
__device__ __forceinline__ void cp16(uint32_t dst, const void* src) {
    asm volatile("cp.async.cg.shared.global [%0], [%1], 16;" :: "r"(dst), "l"(src) : "memory");
}
#define CP_COMMIT() asm volatile("cp.async.commit_group;" ::: "memory")
#define CP_WAIT0()  asm volatile("cp.async.wait_group 0;"  ::: "memory")
#define BAR_SYNC(id)   asm volatile("bar.sync %0, 384;"   :: "r"(id) : "memory")
#define BAR_ARRIVE(id) asm volatile("bar.arrive %0, 384;" :: "r"(id) : "memory")

// ===========================================================================
// GEMM 2 (warp-specialized, single fp16 MMA, BK=128):
//   out = ELU( (adj^2) @ support + bias )
// BM=128, BN=128, BK=128. 384 threads: warps 0-7 consumers, 8-11 producers.
// 3-stage smem ring (68KB/stage), lag-1 cp signaling.
// Consumer: frag double-buffer, LDSM(kk+1) overlaps 16 MMAs of kk.
// ===========================================================================
#define PITCH 272                           // 128 fp16 = 256B + 16 pad (odd x16)
#define G2_AT   (128 * PITCH)               // 34816
#define G2_BT   (128 * PITCH)               // 34816
#define G2_STAGE (G2_AT + G2_BT)            // 69632
#define G2_SMEM  (3 * G2_STAGE)             // 208896

__global__ __launch_bounds__(384, 1)
void gemm2_ws(const float* __restrict__ adj,
              const uint16_t* __restrict__ Bh,
              const float* __restrict__ bias, float* __restrict__ C)
{
    extern __shared__ __align__(128) char smem[];
    const uint32_t sbase = smem_u32(smem);
    const int tid = threadIdx.x;
    const int wid = tid >> 5, lid = tid & 31;
    const int bm = blockIdx.y * 128;
    const int bn = blockIdx.x * 128;
    const int nkt = N_NODES / 128;   // 64

    if (wid >= 8) {
        // ================= PRODUCERS (warps 8-11, 128 threads) =============
        const int ptid = tid - 256;
        const int prow = ptid >> 4;          // A rows prow + 8j (j<16)
        const int pch  = ptid & 15;          // k-chunk pch*4 within 64-k half
        const float* Abase = adj + (size_t)(bm + prow) * N_NODES + pch * 4;
        const size_t bsrow = (size_t)(bn + ptid) * N_NODES;

        float4 aReg[16];
        // prefetch half (t=0, h=0)
        #pragma unroll
        for (int j = 0; j < 16; j++)
            aReg[j] = *reinterpret_cast<const float4*>(Abase + (size_t)(8 * j) * N_NODES);

        for (int t = 0; t < nkt; t++) {
            const int s = t - (t / 3) * 3;
            const uint32_t stg_off = s * G2_STAGE;

            if (t >= 1) {                    // lag-1 full signal for t-1
                CP_WAIT0();
                const int tp = t - 1;
                BAR_ARRIVE(1 + (tp - (tp / 3) * 3));
            }
            if (t >= 3) BAR_SYNC(5 + s);     // wait empty

            // B(t): 16 cp.async (256B row of supT)
            {
                const uint32_t dst = sbase + stg_off + G2_AT + ptid * PITCH;
                const size_t src = bsrow + (size_t)t * 128;
                #pragma unroll
                for (int c = 0; c < 16; c++)
                    cp16(dst + c * 16, Bh + src + c * 8);
                CP_COMMIT();
            }

            // A(t): two 64-k halves with rolling prefetch
            #pragma unroll
            for (int h = 0; h < 2; h++) {
                // convert + STS the half currently in aReg
                #pragma unroll
                for (int j = 0; j < 16; j++) {
                    float4 v = aReg[j];
                    v.x *= v.x; v.y *= v.y; v.z *= v.z; v.w *= v.w;
                    __half2 h01 = __floats2half2_rn(v.x, v.y);
                    __half2 h23 = __floats2half2_rn(v.z, v.w);
                    const uint32_t off = (uint32_t)((prow + 8 * j) * PITCH + h * 128 + pch * 8);
                    *reinterpret_cast<uint2*>(smem + stg_off + off) =
                        make_uint2(*reinterpret_cast<uint32_t*>(&h01),
                                   *reinterpret_cast<uint32_t*>(&h23));
                }
                // prefetch next half: (t, h=1) or (t+1, h=0)
                const int koff = (h == 0) ? (t * 128 + 64)
                                          : ((t + 1 < nkt) ? (t + 1) * 128 : -1);
                if (koff >= 0) {
                    #pragma unroll
                    for (int j = 0; j < 16; j++)
                        aReg[j] = *reinterpret_cast<const float4*>(
                            Abase + koff + (size_t)(8 * j) * N_NODES);
                }
            }
        }
        CP_WAIT0();
        {
            const int tp = nkt - 1;
            BAR_ARRIVE(1 + (tp - (tp / 3) * 3));
        }
        return;
    }

    // ================= CONSUMERS (warps 0-7, 256 threads) ==================
    const int wm = (wid & 1) * 64;           // 2 warps in M
    const int wn = (wid >> 1) * 32;          // 4 warps in N
    const int grp = lid >> 2, quad = lid & 3;

    float acc[4][4][4];
    #pragma unroll
    for (int i = 0; i < 4; i++)
        #pragma unroll
        for (int j = 0; j < 4; j++)
            #pragma unroll
            for (int e = 0; e < 4; e++) acc[i][j][e] = 0.0f;

    const uint32_t a_lane_off = (uint32_t)((wm + (lid & 15)) * PITCH + (lid >> 4) * 16);
    const uint32_t b_lane_off = (uint32_t)(G2_AT +
                                (wn + (lid & 7) + ((lid >> 4) << 3)) * PITCH +
                                ((lid >> 3) & 1) * 16);

    uint32_t ah[2][4][4];   // [buf][mt][reg]
    uint32_t bh[2][2][4];   // [buf][np][reg]

    auto LDSM_A = [&](int buf, uint32_t stg, int kk) {
        #pragma unroll
        for (int mt = 0; mt < 4; mt++)
            ldsm_x4(ah[buf][mt], stg + a_lane_off + mt * (16 * PITCH) + kk * 32);
    };
    auto LDSM_B = [&](int buf, uint32_t stg, int kk) {
        #pragma unroll
        for (int np = 0; np < 2; np++)
            ldsm_x4(bh[buf][np], stg + b_lane_off + np * (16 * PITCH) + kk * 32);
    };

    for (int t = 0; t < nkt; t++) {
        const int s = t - (t / 3) * 3;
        const uint32_t stg = sbase + s * G2_STAGE;
        BAR_SYNC(1 + s);                      // wait full

        LDSM_A(0, stg, 0);
        LDSM_B(0, stg, 0);

        #pragma unroll
        for (int kk = 0; kk < 8; kk++) {      // 8 k16 steps in BK=128
            const int cur = kk & 1, nxt = cur ^ 1;
            if (kk < 7) {
                LDSM_A(nxt, stg, kk + 1);
                LDSM_B(nxt, stg, kk + 1);
            } else {
                BAR_ARRIVE(5 + s);            // stage consumed
            }
            #pragma unroll
            for (int mt = 0; mt < 4; mt++)
                #pragma unroll
                for (int nt = 0; nt < 4; nt++)
                    mma16816h(acc[mt][nt],
                              ah[cur][mt][0], ah[cur][mt][1], ah[cur][mt][2], ah[cur][mt][3],
                              bh[cur][nt >> 1][(nt & 1) * 2], bh[cur][nt >> 1][(nt & 1) * 2 + 1]);
        }
    }

    // epilogue: bias + ELU, fp32 stores
    #pragma unroll
    for (int nt = 0; nt < 4; nt++) {
        const int col = bn + wn + nt * 8 + 2 * quad;
        const float bb0 = bias[col], bb1 = bias[col + 1];
        #pragma unroll
        for (int mt = 0; mt < 4; mt++) {
            const int row = bm + wm + mt * 16 + grp;
            float2 v01 = make_float2(acc[mt][nt][0] + bb0, acc[mt][nt][1] + bb1);
            float2 v23 = make_float2(acc[mt][nt][2] + bb0, acc[mt][nt][3] + bb1);
            v01.x = v01.x > 0.0f ? v01.x : expm1f(v01.x);
            v01.y = v01.y > 0.0f ? v01.y : expm1f(v01.y);
            v23.x = v23.x > 0.0f ? v23.x : expm1f(v23.x);
            v23.y = v23.y > 0.0f ? v23.y : expm1f(v23.y);
            *reinterpret_cast<float2*>(C + (size_t)row * OUT_F + col) = v01;
            *reinterpret_cast<float2*>(C + (size_t)(row + 8) * OUT_F + col) = v23;
        }
    }
}

// ===========================================================================
// GEMM 1 (bf16 3-term internal, proven): supT = fp16(input @ weight)^T
// BM=64, BN=128, BK=64, 256 threads, 2 CTA/SM.
// ===========================================================================
#define PITCH_B 144
#define G1_AT   (64 * PITCH_B)
#define G1_BT   (128 * PITCH_B)
#define G1_STAGE (2 * G1_AT + 2 * G1_BT)
#define G1_SMEM  (2 * G1_STAGE)

__global__ __launch_bounds__(256, 2)
void gemm1(const float* __restrict__ A, const float* __restrict__ Bf32,
           uint16_t* __restrict__ outT)
{
    extern __shared__ __align__(128) char smem[];
    const uint32_t sbase = smem_u32(smem);
    const int tid = threadIdx.x;
    const int bm = blockIdx.y * 64;
    const int bn = blockIdx.x * 128;
    const int wid = tid >> 5, lid = tid & 31;
    const int wm = (wid & 1) * 32;
    const int wn = (wid >> 1) * 32;
    const int grp = lid >> 2, quad = lid & 3;

    const int a_row = tid >> 2, a_seg = tid & 3;
    const int b_n = tid & 127, b_kq = tid >> 7;

    float acc[2][4][4];
    #pragma unroll
    for (int i = 0; i < 2; i++)
        #pragma unroll
        for (int j = 0; j < 4; j++)
            #pragma unroll
            for (int e = 0; e < 4; e++) acc[i][j][e] = 0.0f;

    const float* Abase = A + (size_t)(bm + a_row) * IN_F + a_seg * 16;
    const int nkt = IN_F / 64;

    float4 aReg[4];
    float  bReg[8][4];

    auto LDG_A = [&](int t) {
        #pragma unroll
        for (int j = 0; j < 4; j++)
            aReg[j] = *reinterpret_cast<const float4*>(Abase + t * 64 + 4 * j);
    };
    auto STS_A = [&](int s) {
        char* st = smem + s * G1_STAGE;
        uint32_t h[8], l[8];
        #pragma unroll
        for (int j = 0; j < 4; j++) {
            float4 v = aReg[j];
            split2(v.x, v.y, h[2 * j], l[2 * j]);
            split2(v.z, v.w, h[2 * j + 1], l[2 * j + 1]);
        }
        const int off = a_row * PITCH_B + a_seg * 32;
        *reinterpret_cast<uint4*>(st + off)              = make_uint4(h[0], h[1], h[2], h[3]);
        *reinterpret_cast<uint4*>(st + off + 16)         = make_uint4(h[4], h[5], h[6], h[7]);
        *reinterpret_cast<uint4*>(st + G1_AT + off)      = make_uint4(l[0], l[1], l[2], l[3]);
        *reinterpret_cast<uint4*>(st + G1_AT + off + 16) = make_uint4(l[4], l[5], l[6], l[7]);
    };
    auto LDG_B = [&](int t) {
        const float* Bbase = Bf32 + bn + b_n;
        #pragma unroll
        for (int j = 0; j < 8; j++) {
            const int kq = b_kq + 2 * j;
            #pragma unroll
            for (int i = 0; i < 4; i++)
                bReg[j][i] = Bbase[(size_t)(t * 64 + kq * 4 + i) * OUT_F];
        }
    };
    auto STS_B = [&](int s) {
        char* st = smem + s * G1_STAGE + 2 * G1_AT;
        #pragma unroll
        for (int j = 0; j < 8; j++) {
            const int kq = b_kq + 2 * j;
            uint32_t h0, l0, h1, l1;
            split2(bReg[j][0], bReg[j][1], h0, l0);
            split2(bReg[j][2], bReg[j][3], h1, l1);
            const int off = b_n * PITCH_B + kq * 8;
            *reinterpret_cast<uint2*>(st + off)         = make_uint2(h0, h1);
            *reinterpret_cast<uint2*>(st + G1_BT + off) = make_uint2(l0, l1);
        }
    };

    const uint32_t a_lane_off = (uint32_t)((wm + (lid & 15)) * PITCH_B + (lid >> 4) * 16);
    const uint32_t b_lane_off = (uint32_t)(2 * G1_AT +
                                (wn + (lid & 7) + ((lid >> 4) << 3)) * PITCH_B +
                                ((lid >> 3) & 1) * 16);

    auto MMA_KK = [&](uint32_t stg, int kk) {
        uint32_t ah[2][4], al[2][4], bh[2][4], bl[2][4];
        #pragma unroll
        for (int mt = 0; mt < 2; mt++) {
            const uint32_t ad = stg + a_lane_off + mt * (16 * PITCH_B) + kk * 32;
            ldsm_x4(ah[mt], ad);
            ldsm_x4(al[mt], ad + G1_AT);
        }
        #pragma unroll
        for (int np = 0; np < 2; np++) {
            const uint32_t bd = stg + b_lane_off + np * (16 * PITCH_B) + kk * 32;
            ldsm_x4(bh[np], bd);
            ldsm_x4(bl[np], bd + G1_BT);
        }
        #pragma unroll
        for (int mt = 0; mt < 2; mt++)
            #pragma unroll
            for (int nt = 0; nt < 4; nt++) {
                const uint32_t b0h = bh[nt >> 1][(nt & 1) * 2];
                const uint32_t b1h = bh[nt >> 1][(nt & 1) * 2 + 1];
                const uint32_t b0l = bl[nt >> 1][(nt & 1) * 2];
                const uint32_t b1l = bl[nt >> 1][(nt & 1) * 2 + 1];
                mma16816(acc[mt][nt], ah[mt][0], ah[mt][1], ah[mt][2], ah[mt][3], b0h, b1h);
                mma16816(acc[mt][nt], ah[mt][0], ah[mt][1], ah[mt][2], ah[mt][3], b0l, b1l);
                mma16816(acc[mt][nt], al[mt][0], al[mt][1], al[mt][2], al[mt][3], b0h, b1h);
            }
    };

    LDG_A(0); STS_A(0);
    LDG_B(0); STS_B(0);
    __syncthreads();

    for (int t = 0; t < nkt; t++) {
        const int s = t & 1;
        const uint32_t stg = sbase + s * G1_STAGE;
        const bool nx = (t + 1 < nkt);
        if (nx) { LDG_A(t + 1); LDG_B(t + 1); }
        MMA_KK(stg, 0);
        MMA_KK(stg, 1);
        if (nx) { STS_A(s ^ 1); STS_B(s ^ 1); }
        MMA_KK(stg, 2);
        MMA_KK(stg, 3);
        __syncthreads();
    }

    // epilogue: store fp16 support, transposed
    #pragma unroll
    for (int nt = 0; nt < 4; nt++) {
        const int col = bn + wn + nt * 8 + 2 * quad;
        #pragma unroll
        for (int mt = 0; mt < 2; mt++) {
            const int row = bm + wm + mt * 16 + grp;
            __half h;
            h = __float2half_rn(acc[mt][nt][0]);
            outT[(size_t)col * N_NODES + row] = *reinterpret_cast<uint16_t*>(&h);
            h = __float2half_rn(acc[mt][nt][1]);
            outT[(size_t)(col + 1) * N_NODES + row] = *reinterpret_cast<uint16_t*>(&h);
            h = __float2half_rn(acc[mt][nt][2]);
            outT[(size_t)col * N_NODES + row + 8] = *reinterpret_cast<uint16_t*>(&h);
            h = __float2half_rn(acc[mt][nt][3]);
            outT[(size_t)(col + 1) * N_NODES + row + 8] = *reinterpret_cast<uint16_t*>(&h);
        }
    }
}

extern "C" void kernel_launch(void* const* d_in, const int* in_sizes, int n_in,
                              void* d_out, int out_size)
{
    const float* input  = (const float*)d_in[0];  // [8192, 512]
    const float* adj    = (const float*)d_in[1];  // [8192, 8192]
    const float* weight = (const float*)d_in[2];  // [512, 256]
    const float* bias   = (const float*)d_in[3];  // [256]
    float* out = (float*)d_out;                   // [8192, 256]

    uint16_t* supT = nullptr;
    cudaGetSymbolAddress((void**)&supT, g_supT);

    cudaFuncSetAttribute(gemm1, cudaFuncAttributeMaxDynamicSharedMemorySize, G1_SMEM);
    cudaFuncSetAttribute(gemm2_ws, cudaFuncAttributeMaxDynamicSharedMemorySize, G2_SMEM);

    // GEMM 1: supT = fp16(input @ weight)^T
    {
        dim3 grid(OUT_F / 128, N_NODES / 64);   // (2, 128)
        gemm1<<<grid, 256, G1_SMEM>>>(input, weight, supT);
    }
    // GEMM 2: out = ELU( (adj^2) @ support + bias )
    {
        dim3 grid(OUT_F / 128, N_NODES / 128);  // (2, 64) = 128 CTAs
        gemm2_ws<<<grid, 384, G2_SMEM>>>(adj, supT, bias, out);
    }
}

// round 13
// speedup vs baseline: 1.3264x; 1.3264x over previous
#include <cuda_runtime.h>
#include <cuda_fp16.h>
#include <stdint.h>
#include <math.h>

#define N_NODES 8192
#define IN_F    512
#define OUT_F   256

// support as fp16, TRANSPOSED: [OUT_F][N_NODES]
__device__ uint16_t g_supT[OUT_F * N_NODES];

__device__ __forceinline__ uint32_t smem_u32(const void* p) {
    uint32_t a;
    asm("{ .reg .u64 t; cvta.to.shared.u64 t, %1; cvt.u32.u64 %0, t; }" : "=r"(a) : "l"(p));
    return a;
}
__device__ __forceinline__ void ldsm_x4(uint32_t r[4], uint32_t addr) {
    asm volatile("ldmatrix.sync.aligned.m8n8.x4.shared.b16 {%0,%1,%2,%3}, [%4];"
                 : "=r"(r[0]), "=r"(r[1]), "=r"(r[2]), "=r"(r[3]) : "r"(addr));
}
__device__ __forceinline__ void mma16816h(float c[4],
                                          uint32_t a0, uint32_t a1, uint32_t a2, uint32_t a3,
                                          uint32_t b0, uint32_t b1) {
    asm volatile(
        "mma.sync.aligned.m16n8k16.row.col.f32.f16.f16.f32 "
        "{%0,%1,%2,%3}, {%4,%5,%6,%7}, {%8,%9}, {%0,%1,%2,%3};"
        : "+f"(c[0]), "+f"(c[1]), "+f"(c[2]), "+f"(c[3])
        : "r"(a0), "r"(a1), "r"(a2), "r"(a3), "r"(b0), "r"(b1));
}
__device__ __forceinline__ void cp16(uint32_t dst, const void* src) {
    asm volatile("cp.async.cg.shared.global [%0], [%1], 16;" :: "r"(dst), "l"(src) : "memory");
}
#define CP_COMMIT() asm volatile("cp.async.commit_group;" ::: "memory")
#define CP_WAIT0()  asm volatile("cp.async.wait_group 0;"  ::: "memory")
#define BAR_SYNC(id)   asm volatile("bar.sync %0, 384;"   :: "r"(id) : "memory")
#define BAR_ARRIVE(id) asm volatile("bar.arrive %0, 384;" :: "r"(id) : "memory")

// ===========================================================================
// GEMM 2 (R11 EXACT, proven 153.5us): out = ELU( (adj^2) @ support + bias )
// BM=128, BN=128, BK=64. 384 threads: warps 0-7 consumers, 8-11 producers.
// 4-stage smem ring, lag-1 cp signaling. Stage = [A fp16 | B fp16].
// ===========================================================================
#define PITCH_B 144
#define G2_AT   (128 * PITCH_B)            // 18432
#define G2_BT   (128 * PITCH_B)            // 18432
#define G2_STAGE (G2_AT + G2_BT)           // 36864
#define G2_SMEM  (4 * G2_STAGE)            // 147456

__global__ __launch_bounds__(384, 1)
void gemm2_ws(const float* __restrict__ adj,
              const uint16_t* __restrict__ Bh,
              const float* __restrict__ bias, float* __restrict__ C)
{
    extern __shared__ __align__(128) char smem[];
    const uint32_t sbase = smem_u32(smem);
    const int tid = threadIdx.x;
    const int wid = tid >> 5, lid = tid & 31;
    const int bm = blockIdx.y * 128;
    const int bn = blockIdx.x * 128;
    const int nkt = N_NODES / 64;   // 128

    if (wid >= 8) {
        // ================= PRODUCERS (warps 8-11, 128 threads) =============
        const int ptid = tid - 256;
        const int prow = ptid >> 4;
        const int pch  = ptid & 15;
        const float* Abase = adj + (size_t)(bm + prow) * N_NODES + pch * 4;
        const size_t bsrow = (size_t)(bn + ptid) * N_NODES;

        float4 aReg[16];
        #pragma unroll
        for (int j = 0; j < 16; j++)
            aReg[j] = *reinterpret_cast<const float4*>(Abase + (size_t)(8 * j) * N_NODES);

        for (int t = 0; t < nkt; t++) {
            const int s = t & 3;
            const uint32_t stg_off = s * G2_STAGE;

            if (t >= 1) {
                CP_WAIT0();
                BAR_ARRIVE(1 + ((t - 1) & 3));
            }
            if (t >= 4) BAR_SYNC(5 + s);

            {
                const uint32_t dst = sbase + stg_off + G2_AT + ptid * PITCH_B;
                const size_t src = bsrow + (size_t)t * 64;
                #pragma unroll
                for (int c = 0; c < 8; c++)
                    cp16(dst + c * 16, Bh + src + c * 8);
                CP_COMMIT();
            }

            #pragma unroll
            for (int j = 0; j < 16; j++) {
                float4 v = aReg[j];
                v.x *= v.x; v.y *= v.y; v.z *= v.z; v.w *= v.w;
                __half2 h01 = __floats2half2_rn(v.x, v.y);
                __half2 h23 = __floats2half2_rn(v.z, v.w);
                const uint32_t off = (uint32_t)((prow + 8 * j) * PITCH_B + pch * 8);
                *reinterpret_cast<uint2*>(smem + stg_off + off) =
                    make_uint2(*reinterpret_cast<uint32_t*>(&h01),
                               *reinterpret_cast<uint32_t*>(&h23));
            }

            if (t + 1 < nkt) {
                #pragma unroll
                for (int j = 0; j < 16; j++)
                    aReg[j] = *reinterpret_cast<const float4*>(
                        Abase + (t + 1) * 64 + (size_t)(8 * j) * N_NODES);
            }
        }
        CP_WAIT0();
        BAR_ARRIVE(1 + ((nkt - 1) & 3));
        return;
    }

    // ================= CONSUMERS (warps 0-7, 256 threads) ==================
    const int wm = (wid & 1) * 64;
    const int wn = (wid >> 1) * 32;
    const int grp = lid >> 2, quad = lid & 3;

    float acc[4][4][4];
    #pragma unroll
    for (int i = 0; i < 4; i++)
        #pragma unroll
        for (int j = 0; j < 4; j++)
            #pragma unroll
            for (int e = 0; e < 4; e++) acc[i][j][e] = 0.0f;

    const uint32_t a_lane_off = (uint32_t)((wm + (lid & 15)) * PITCH_B + (lid >> 4) * 16);
    const uint32_t b_lane_off = (uint32_t)(G2_AT +
                                (wn + (lid & 7) + ((lid >> 4) << 3)) * PITCH_B +
                                ((lid >> 3) & 1) * 16);

    for (int t = 0; t < nkt; t++) {
        const int s = t & 3;
        const uint32_t stg = sbase + s * G2_STAGE;
        BAR_SYNC(1 + s);

        #pragma unroll
        for (int kk = 0; kk < 4; kk++) {
            uint32_t ah[4][4], bh[2][4];
            #pragma unroll
            for (int mt = 0; mt < 4; mt++)
                ldsm_x4(ah[mt], stg + a_lane_off + mt * (16 * PITCH_B) + kk * 32);
            #pragma unroll
            for (int np = 0; np < 2; np++)
                ldsm_x4(bh[np], stg + b_lane_off + np * (16 * PITCH_B) + kk * 32);
            if (kk == 3) BAR_ARRIVE(5 + s);
            #pragma unroll
            for (int mt = 0; mt < 4; mt++)
                #pragma unroll
                for (int nt = 0; nt < 4; nt++)
                    mma16816h(acc[mt][nt],
                              ah[mt][0], ah[mt][1], ah[mt][2], ah[mt][3],
                              bh[nt >> 1][(nt & 1) * 2], bh[nt >> 1][(nt & 1) * 2 + 1]);
        }
    }

    #pragma unroll
    for (int nt = 0; nt < 4; nt++) {
        const int col = bn + wn + nt * 8 + 2 * quad;
        const float bb0 = bias[col], bb1 = bias[col + 1];
        #pragma unroll
        for (int mt = 0; mt < 4; mt++) {
            const int row = bm + wm + mt * 16 + grp;
            float2 v01 = make_float2(acc[mt][nt][0] + bb0, acc[mt][nt][1] + bb1);
            float2 v23 = make_float2(acc[mt][nt][2] + bb0, acc[mt][nt][3] + bb1);
            v01.x = v01.x > 0.0f ? v01.x : expm1f(v01.x);
            v01.y = v01.y > 0.0f ? v01.y : expm1f(v01.y);
            v23.x = v23.x > 0.0f ? v23.x : expm1f(v23.x);
            v23.y = v23.y > 0.0f ? v23.y : expm1f(v23.y);
            *reinterpret_cast<float2*>(C + (size_t)row * OUT_F + col) = v01;
            *reinterpret_cast<float2*>(C + (size_t)(row + 8) * OUT_F + col) = v23;
        }
    }
}

// ===========================================================================
// GEMM 1 (now fp16 single-term): supT = fp16(input @ weight)^T
// BM=64, BN=128, BK=64, 256 threads, 2 CTA/SM.
// Stage = [A fp16 | B fp16] (hi-only), single fp16 MMA per k16.
// ===========================================================================
#define G1_AT   (64 * PITCH_B)              // 9216
#define G1_BT   (128 * PITCH_B)             // 18432
#define G1_STAGE (G1_AT + G1_BT)            // 27648
#define G1_SMEM  (2 * G1_STAGE)             // 55296

__global__ __launch_bounds__(256, 2)
void gemm1(const float* __restrict__ A, const float* __restrict__ Bf32,
           uint16_t* __restrict__ outT)
{
    extern __shared__ __align__(128) char smem[];
    const uint32_t sbase = smem_u32(smem);
    const int tid = threadIdx.x;
    const int bm = blockIdx.y * 64;
    const int bn = blockIdx.x * 128;
    const int wid = tid >> 5, lid = tid & 31;
    const int wm = (wid & 1) * 32;
    const int wn = (wid >> 1) * 32;
    const int grp = lid >> 2, quad = lid & 3;

    const int a_row = tid >> 2, a_seg = tid & 3;
    const int b_n = tid & 127, b_kq = tid >> 7;

    float acc[2][4][4];
    #pragma unroll
    for (int i = 0; i < 2; i++)
        #pragma unroll
        for (int j = 0; j < 4; j++)
            #pragma unroll
            for (int e = 0; e < 4; e++) acc[i][j][e] = 0.0f;

    const float* Abase = A + (size_t)(bm + a_row) * IN_F + a_seg * 16;
    const int nkt = IN_F / 64;

    float4 aReg[4];
    float  bReg[8][4];

    auto LDG_A = [&](int t) {
        #pragma unroll
        for (int j = 0; j < 4; j++)
            aReg[j] = *reinterpret_cast<const float4*>(Abase + t * 64 + 4 * j);
    };
    // A: 16 consecutive k per thread -> 16 fp16 = 32B
    auto STS_A = [&](int s) {
        char* st = smem + s * G1_STAGE;
        uint32_t h[8];
        #pragma unroll
        for (int j = 0; j < 4; j++) {
            float4 v = aReg[j];
            __half2 h01 = __floats2half2_rn(v.x, v.y);
            __half2 h23 = __floats2half2_rn(v.z, v.w);
            h[2 * j]     = *reinterpret_cast<uint32_t*>(&h01);
            h[2 * j + 1] = *reinterpret_cast<uint32_t*>(&h23);
        }
        const int off = a_row * PITCH_B + a_seg * 32;
        *reinterpret_cast<uint4*>(st + off)      = make_uint4(h[0], h[1], h[2], h[3]);
        *reinterpret_cast<uint4*>(st + off + 16) = make_uint4(h[4], h[5], h[6], h[7]);
    };
    auto LDG_B = [&](int t) {
        const float* Bbase = Bf32 + bn + b_n;
        #pragma unroll
        for (int j = 0; j < 8; j++) {
            const int kq = b_kq + 2 * j;
            #pragma unroll
            for (int i = 0; i < 4; i++)
                bReg[j][i] = Bbase[(size_t)(t * 64 + kq * 4 + i) * OUT_F];
        }
    };
    auto STS_B = [&](int s) {
        char* st = smem + s * G1_STAGE + G1_AT;
        #pragma unroll
        for (int j = 0; j < 8; j++) {
            const int kq = b_kq + 2 * j;
            __half2 h01 = __floats2half2_rn(bReg[j][0], bReg[j][1]);
            __half2 h23 = __floats2half2_rn(bReg[j][2], bReg[j][3]);
            const int off = b_n * PITCH_B + kq * 8;
            *reinterpret_cast<uint2*>(st + off) =
                make_uint2(*reinterpret_cast<uint32_t*>(&h01),
                           *reinterpret_cast<uint32_t*>(&h23));
        }
    };

    const uint32_t a_lane_off = (uint32_t)((wm + (lid & 15)) * PITCH_B + (lid >> 4) * 16);
    const uint32_t b_lane_off = (uint32_t)(G1_AT +
                                (wn + (lid & 7) + ((lid >> 4) << 3)) * PITCH_B +
                                ((lid >> 3) & 1) * 16);

    auto MMA_KK = [&](uint32_t stg, int kk) {
        uint32_t ah[2][4], bh[2][4];
        #pragma unroll
        for (int mt = 0; mt < 2; mt++)
            ldsm_x4(ah[mt], stg + a_lane_off + mt * (16 * PITCH_B) + kk * 32);
        #pragma unroll
        for (int np = 0; np < 2; np++)
            ldsm_x4(bh[np], stg + b_lane_off + np * (16 * PITCH_B) + kk * 32);
        #pragma unroll
        for (int mt = 0; mt < 2; mt++)
            #pragma unroll
            for (int nt = 0; nt < 4; nt++)
                mma16816h(acc[mt][nt],
                          ah[mt][0], ah[mt][1], ah[mt][2], ah[mt][3],
                          bh[nt >> 1][(nt & 1) * 2], bh[nt >> 1][(nt & 1) * 2 + 1]);
    };

    LDG_A(0); STS_A(0);
    LDG_B(0); STS_B(0);
    __syncthreads();

    for (int t = 0; t < nkt; t++) {
        const int s = t & 1;
        const uint32_t stg = sbase + s * G1_STAGE;
        const bool nx = (t + 1 < nkt);
        if (nx) { LDG_A(t + 1); LDG_B(t + 1); }
        MMA_KK(stg, 0);
        MMA_KK(stg, 1);
        if (nx) { STS_A(s ^ 1); STS_B(s ^ 1); }
        MMA_KK(stg, 2);
        MMA_KK(stg, 3);
        __syncthreads();
    }

    // epilogue: store fp16 support, transposed
    #pragma unroll
    for (int nt = 0; nt < 4; nt++) {
        const int col = bn + wn + nt * 8 + 2 * quad;
        #pragma unroll
        for (int mt = 0; mt < 2; mt++) {
            const int row = bm + wm + mt * 16 + grp;
            __half h;
            h = __float2half_rn(acc[mt][nt][0]);
            outT[(size_t)col * N_NODES + row] = *reinterpret_cast<uint16_t*>(&h);
            h = __float2half_rn(acc[mt][nt][1]);
            outT[(size_t)(col + 1) * N_NODES + row] = *reinterpret_cast<uint16_t*>(&h);
            h = __float2half_rn(acc[mt][nt][2]);
            outT[(size_t)col * N_NODES + row + 8] = *reinterpret_cast<uint16_t*>(&h);
            h = __float2half_rn(acc[mt][nt][3]);
            outT[(size_t)(col + 1) * N_NODES + row + 8] = *reinterpret_cast<uint16_t*>(&h);
        }
    }
}

extern "C" void kernel_launch(void* const* d_in, const int* in_sizes, int n_in,
                              void* d_out, int out_size)
{
    const float* input  = (const float*)d_in[0];  // [8192, 512]
    const float* adj    = (const float*)d_in[1];  // [8192, 8192]
    const float* weight = (const float*)d_in[2];  // [512, 256]
    const float* bias   = (const float*)d_in[3];  // [256]
    float* out = (float*)d_out;                   // [8192, 256]

    uint16_t* supT = nullptr;
    cudaGetSymbolAddress((void**)&supT, g_supT);

    cudaFuncSetAttribute(gemm1, cudaFuncAttributeMaxDynamicSharedMemorySize, G1_SMEM);
    cudaFuncSetAttribute(gemm2_ws, cudaFuncAttributeMaxDynamicSharedMemorySize, G2_SMEM);

    // GEMM 1: supT = fp16(input @ weight)^T
    {
        dim3 grid(OUT_F / 128, N_NODES / 64);   // (2, 128)
        gemm1<<<grid, 256, G1_SMEM>>>(input, weight, supT);
    }
    // GEMM 2: out = ELU( (adj^2) @ support + bias )
    {
        dim3 grid(OUT_F / 128, N_NODES / 128);  // (2, 64) = 128 CTAs
        gemm2_ws<<<grid, 384, G2_SMEM>>>(adj, supT, bias, out);
    }
}